// round 14
// baseline (speedup 1.0000x reference)
#include <cuda_runtime.h>
#include <cuda_fp16.h>

static constexpr int TOK   = 64;     // tokens per sequence
static constexpr int D     = 512;    // embedding dim
static constexpr int NC    = 64;     // classes
static constexpr int QN    = 2048;   // queries
static constexpr int SN    = 4096;   // supports
static constexpr int VOCAB = 32000;

// GEMM: proto_raw[64 x 32000-hist] @ table_h[32000 x 512]
static constexpr int KS     = 125;           // K splits
static constexpr int KCHUNK = VOCAB / KS;    // 256
static constexpr int NITER  = KCHUNK / 16;   // 16
static constexpr int NT     = 4;             // N tiles of 128 (pgemm grid = 500)

// k_front role boundaries (block index): convert then hist
static constexpr int FB_CONV = 8000;
static constexpr int FB_HIST = FB_CONV + 1024;

// k_mid role boundaries: pgemm then query gather (2 rows/block)
static constexpr int MB_GEMM   = NT * KS;            // 500
static constexpr int MB_GATHER = MB_GEMM + QN / 2;   // + 1024

// k_out tiling: 32q x 64c x 64d per block, 8 d-splits -> grid 512
static constexpr int DS  = 8;                // d splits (64 dims each)
static constexpr int QB2 = QN / 32;          // 64 q blocks
static constexpr int TP  = 68;               // padded tile row stride (floats)

// Scratch (__device__ globals; zero-initialized at module load).
// INVARIANT: g_W and g_cnt are ZERO at entry of every kernel_launch call —
// module-load zeros for call 1; k_reduce re-zeros W, k_out re-zeros cnt.
__device__ __align__(16) __half g_table_h[VOCAB * D]; // fp16 shadow (32.8 MB)
__device__ __align__(16) __half g_W[NC * VOCAB];      // class-token histogram (4.1 MB)
__device__ __align__(16) float g_pp[KS * NC * D];     // split-K partials (16.4 MB)
__device__ float g_proto[NC * D];   // normalized prototypes (after k_reduce)
__device__ float g_cnt[NC];         // per-class support-row counts
__device__ float g_qemb[QN * D];    // query embeddings (mean-pooled)
__device__ float g_q2[QN];          // ||q||^2

__device__ __forceinline__ unsigned smem_u32(const void* p) {
    unsigned a;
    asm("{ .reg .u64 t; cvta.to.shared.u64 t, %1; cvt.u32.u64 %0, t; }"
        : "=r"(a) : "l"(p));
    return a;
}

// ---------------------------------------------------------------- kernel 1
// Front end: [0,8000) table fp32 -> fp16 convert; [8000,9024) support hist.
__global__ __launch_bounds__(256) void k_front(
    const int*   __restrict__ s_toks,
    const int*   __restrict__ labels,
    const float* __restrict__ table)
{
    const int bid = blockIdx.x;
    const int tid = threadIdx.x;

    if (bid < FB_CONV) {
        const int i = bid * 256 + tid;               // 8-elem group id
        const float4* sp4 = (const float4*)table;
        float4 a = sp4[2 * i];
        float4 b = sp4[2 * i + 1];
        __half2 h0 = __floats2half2_rn(a.x, a.y);
        __half2 h1 = __floats2half2_rn(a.z, a.w);
        __half2 h2 = __floats2half2_rn(b.x, b.y);
        __half2 h3 = __floats2half2_rn(b.z, b.w);
        uint4 o;
        o.x = *(const unsigned*)&h0;
        o.y = *(const unsigned*)&h1;
        o.z = *(const unsigned*)&h2;
        o.w = *(const unsigned*)&h3;
        ((uint4*)g_table_h)[i] = o;
    } else {
        const int t   = (bid - FB_CONV) * 256 + tid; // < SN*TOK
        const int row = t >> 6;
        const int c   = labels[row];
        const int v   = s_toks[t];
        const int idx = c * VOCAB + v;
        __half2* p = (__half2*)(g_W + (idx & ~1));
        const __half2 one = (idx & 1)
            ? __halves2half2(__ushort_as_half(0), __float2half(1.0f))
            : __halves2half2(__float2half(1.0f), __ushort_as_half(0));
        atomicAdd(p, one);
        if ((t & 63) == 0) atomicAdd(&g_cnt[c], 1.0f);
    }
}

// ---------------------------------------------------------------- kernel 2
// Mid stage, role-split: [0,500) split-K tensor-core proto GEMM;
// [500,1524) query gather on the fp16 shadow (2 rows per block).
// Gather also initializes out[q][*] = -q2[q] (base for k_out's atomics).
__global__ __launch_bounds__(256) void k_mid(
    const int* __restrict__ q_toks, float* __restrict__ out)
{
    const int tid = threadIdx.x;

    if (blockIdx.x < MB_GEMM) {
        // ================= proto GEMM (proven R9-R13 core) =================
        __shared__ __half sA[64 * 24];
        __shared__ __half sB[16 * 136];

        const int bn = (blockIdx.x & (NT - 1)) * 128;
        const int kb = blockIdx.x / NT;
        const int k0 = kb * KCHUNK;
        const int warp = tid >> 5;
        const int lane = tid & 31;
        const int wr   = warp & 3;
        const int wn   = warp >> 2;
        const int g    = lane >> 2;
        const int tg   = lane & 3;

        const int arow  = (tid & 127) >> 1;
        const int acol8 = (tid & 1) * 8;
        const int brow  = tid >> 4;
        const int bcol8 = (tid & 15) * 8;

        const __half* aSrc = g_W + (size_t)arow * VOCAB + k0 + acol8;
        const __half* bSrc = g_table_h + (size_t)(k0 + brow) * D + bn + bcol8;

        const int am = lane >> 3, ar = lane & 7;
        const unsigned aAddr = smem_u32(sA + (wr * 16 + ar + 8 * (am & 1)) * 24
                                           + 8 * (am >> 1));
        const unsigned bAddr = smem_u32(sB + (lane & 15) * 136 + wn * 64);

        float acc[8][4];
        #pragma unroll
        for (int s = 0; s < 8; ++s)
            acc[s][0] = acc[s][1] = acc[s][2] = acc[s][3] = 0.0f;

        uint4 va = make_uint4(0, 0, 0, 0);
        if (tid < 128) va = *(const uint4*)(aSrc);
        uint4 vb = *(const uint4*)(bSrc);

        for (int it = 0; it < NITER; ++it) {
            __syncthreads();
            if (tid < 128) *(uint4*)(sA + arow * 24 + acol8) = va;
            *(uint4*)(sB + brow * 136 + bcol8) = vb;
            __syncthreads();

            const int kn = min((it + 1) * 16, KCHUNK - 16);
            if (tid < 128) va = *(const uint4*)(aSrc + kn);
            vb = *(const uint4*)(bSrc + (size_t)kn * D);

            unsigned a0, a1, a2, a3;
            asm volatile("ldmatrix.sync.aligned.m8n8.x4.shared.b16 {%0,%1,%2,%3}, [%4];"
                         : "=r"(a0), "=r"(a1), "=r"(a2), "=r"(a3) : "r"(aAddr));
            #pragma unroll
            for (int s = 0; s < 8; ++s) {
                unsigned b0, b1;
                asm volatile("ldmatrix.sync.aligned.m8n8.x2.trans.shared.b16 {%0,%1}, [%2];"
                             : "=r"(b0), "=r"(b1) : "r"(bAddr + s * 16));
                asm volatile(
                    "mma.sync.aligned.m16n8k16.row.col.f32.f16.f16.f32 "
                    "{%0,%1,%2,%3}, {%4,%5,%6,%7}, {%8,%9}, {%0,%1,%2,%3};"
                    : "+f"(acc[s][0]), "+f"(acc[s][1]), "+f"(acc[s][2]), "+f"(acc[s][3])
                    : "r"(a0), "r"(a1), "r"(a2), "r"(a3), "r"(b0), "r"(b1));
            }
        }

        float* base = g_pp + (size_t)kb * NC * D;
        #pragma unroll
        for (int s = 0; s < 8; ++s) {
            const int col = bn + wn * 64 + s * 8 + tg * 2;
            *(float2*)(base + (wr * 16 + g) * D + col)     =
                make_float2(acc[s][0], acc[s][1]);
            *(float2*)(base + (wr * 16 + g + 8) * D + col) =
                make_float2(acc[s][2], acc[s][3]);
        }
    } else {
        // ================= query gather on fp16 shadow =================
        const int bid = blockIdx.x - MB_GEMM;
        const int h   = tid >> 7;            // 0 or 1
        const int lt  = tid & 127;           // lane within half-block
        const int row = bid * 2 + h;

        __shared__ int sh_tok[2][TOK];
        __shared__ float sp[8];
        __shared__ float sq2[2];
        if (lt < TOK)
            sh_tok[h][lt] = q_toks[(size_t)row * TOK + lt];
        __syncthreads();

        float a0 = 0.f, a1 = 0.f, a2 = 0.f, a3 = 0.f;
        #pragma unroll 8
        for (int j = 0; j < TOK; ++j) {
            const uint2* r = (const uint2*)(g_table_h + (size_t)sh_tok[h][j] * D);
            uint2 v = r[lt];                           // 4 halves
            float2 f0 = __half22float2(*(const __half2*)&v.x);
            float2 f1 = __half22float2(*(const __half2*)&v.y);
            a0 += f0.x; a1 += f0.y; a2 += f1.x; a3 += f1.y;
        }
        const float s = 1.0f / (float)TOK;
        a0 *= s; a1 *= s; a2 *= s; a3 *= s;
        ((float4*)(g_qemb + (size_t)row * D))[lt] = make_float4(a0, a1, a2, a3);

        float qq = a0*a0 + a1*a1 + a2*a2 + a3*a3;
        #pragma unroll
        for (int o = 16; o > 0; o >>= 1)
            qq += __shfl_down_sync(0xFFFFFFFFu, qq, o);
        if ((tid & 31) == 0) sp[tid >> 5] = qq;
        __syncthreads();
        if (lt == 0) {
            const float v = sp[h * 4] + sp[h * 4 + 1] + sp[h * 4 + 2] + sp[h * 4 + 3];
            g_q2[row] = v;
            sq2[h] = v;
        }
        __syncthreads();
        // out init: out[row][c] = -q2[row] for all 64 classes (16 float4).
        const float nq2 = -sq2[h];
        if (lt < 16)
            ((float4*)(out + (size_t)row * NC))[lt] =
                make_float4(nq2, nq2, nq2, nq2);
    }
}

// ---------------------------------------------------------------- kernel 3
// Fold split-K partials + 1/(64*cnt) normalization into g_proto.
// Also re-zero g_W (not touched by this kernel) for the next call.
__global__ __launch_bounds__(256) void k_reduce()
{
    const int t = blockIdx.x * blockDim.x + threadIdx.x;   // < 32768 = NC*D
    float a = 0.0f;
    #pragma unroll 5
    for (int s = 0; s < KS; ++s) a += g_pp[(size_t)s * NC * D + t];
    const int c = t >> 9;                                  // t / D
    g_proto[t] = a / (64.0f * fmaxf(g_cnt[c], 1.0f));

    // W re-zero: g_W = NC*VOCAB/8 = 256000 uint4 (guarded)
    uint4* w4 = (uint4*)g_W;
    #pragma unroll
    for (int r = 0; r < 8; ++r) {
        const int idx = t + r * 32768;
        if (idx < NC * VOCAB / 8) w4[idx] = make_uint4(0, 0, 0, 0);
    }
}

// ---------------------------------------------------------------- kernel 4
// Distance GEMM: block = 32q x 64c x 64d; grid = 64 q-blocks x 8 d-splits
// = 512 (>3 blocks/SM, no partial-wave tail). 2q x 4c register tile.
// Adds 2*dot_s - p2_s atomically onto the -q2 base. Trailing: zero g_cnt.
__global__ __launch_bounds__(256) void k_out(float* __restrict__ out)
{
    __shared__ __align__(16) float q_s[32 * TP];
    __shared__ __align__(16) float p_s[64 * TP];
    __shared__ float s_pp[NC];

    const int tid = threadIdx.x;
    const int q0  = (blockIdx.x >> 3) * 32;       // q block
    const int d0  = (blockIdx.x & 7) * 64;        // d split

    // Stage q tile: 32 rows x 16 float4 (2 per thread), coalesced.
    #pragma unroll
    for (int r = 0; r < 2; ++r) {
        const int idx  = tid + r * 256;           // < 512
        const int row  = idx >> 4;
        const int col4 = idx & 15;
        ((float4*)(q_s + row * TP))[col4] =
            ((const float4*)(g_qemb + (size_t)(q0 + row) * D + d0))[col4];
    }
    // Stage p tile: 64 rows x 16 float4 (4 per thread), coalesced.
    #pragma unroll
    for (int r = 0; r < 4; ++r) {
        const int idx  = tid + r * 256;           // < 1024
        const int row  = idx >> 4;
        const int col4 = idx & 15;
        ((float4*)(p_s + row * TP))[col4] =
            ((const float4*)(g_proto + (size_t)row * D + d0))[col4];
    }
    __syncthreads();

    const int tq = tid >> 4;       // 0..15 -> q rows 2tq, 2tq+1
    const int tc = tid & 15;       // c rows tc, tc+16, tc+32, tc+48

    float acc[2][4];
    #pragma unroll
    for (int i = 0; i < 2; ++i)
        acc[i][0] = acc[i][1] = acc[i][2] = acc[i][3] = 0.0f;
    float pa0 = 0.f, pa1 = 0.f, pa2 = 0.f, pa3 = 0.f;

    #pragma unroll 4
    for (int d4 = 0; d4 < 16; ++d4) {
        float4 pv[4];
        #pragma unroll
        for (int j = 0; j < 4; ++j)
            pv[j] = ((const float4*)(p_s + (tc + 16 * j) * TP))[d4];
        if (tq == 0) {   // p2 partials (one owner per class)
            pa0 += pv[0].x*pv[0].x + pv[0].y*pv[0].y + pv[0].z*pv[0].z + pv[0].w*pv[0].w;
            pa1 += pv[1].x*pv[1].x + pv[1].y*pv[1].y + pv[1].z*pv[1].z + pv[1].w*pv[1].w;
            pa2 += pv[2].x*pv[2].x + pv[2].y*pv[2].y + pv[2].z*pv[2].z + pv[2].w*pv[2].w;
            pa3 += pv[3].x*pv[3].x + pv[3].y*pv[3].y + pv[3].z*pv[3].z + pv[3].w*pv[3].w;
        }
        #pragma unroll
        for (int i = 0; i < 2; ++i) {
            const float4 qv = ((const float4*)(q_s + (2 * tq + i) * TP))[d4];
            #pragma unroll
            for (int j = 0; j < 4; ++j)
                acc[i][j] += qv.x*pv[j].x + qv.y*pv[j].y
                           + qv.z*pv[j].z + qv.w*pv[j].w;
        }
    }

    if (tq == 0) {
        s_pp[tc]      = pa0;
        s_pp[tc + 16] = pa1;
        s_pp[tc + 32] = pa2;
        s_pp[tc + 48] = pa3;
    }
    __syncthreads();

    #pragma unroll
    for (int i = 0; i < 2; ++i) {
        const int q = q0 + 2 * tq + i;
        #pragma unroll
        for (int j = 0; j < 4; ++j) {
            const int c = tc + 16 * j;
            atomicAdd(out + (size_t)q * NC + c, 2.0f * acc[i][j] - s_pp[c]);
        }
    }

    // cnt re-zero for next call (cnt is not read by this kernel).
    const int t = blockIdx.x * 256 + tid;
    if (t < NC) g_cnt[t] = 0.0f;
}

// ----------------------------------------------------------------
extern "C" void kernel_launch(void* const* d_in, const int* in_sizes, int n_in,
                              void* d_out, int out_size)
{
    // JAX x64 disabled -> "int64" tensors are int32 on the wire.
    const int*   query   = (const int*)d_in[0];
    const int*   support = (const int*)d_in[1];
    const int*   labels  = (const int*)d_in[2];
    const float* table   = (const float*)d_in[3];
    float* out = (float*)d_out;

    k_front<<<FB_HIST, 256>>>(support, labels, table);  // convert + hist
    k_mid<<<MB_GATHER, 256>>>(query, out);              // GEMM ∥ gather (+init)
    k_reduce<<<NC * D / 256, 256>>>();                  // fold splits + W zero
    k_out<<<QB2 * DS, 256>>>(out);                      // distances
}

// round 16
// speedup vs baseline: 1.0199x; 1.0199x over previous
#include <cuda_runtime.h>
#include <cuda_fp16.h>

static constexpr int TOK   = 64;     // tokens per sequence
static constexpr int D     = 512;    // embedding dim
static constexpr int NC    = 64;     // classes
static constexpr int QN    = 2048;   // queries
static constexpr int SN    = 4096;   // supports
static constexpr int VOCAB = 32000;

// GEMM: proto_raw[64 x 32000-hist] @ table_h[32000 x 512]
static constexpr int KS     = 125;           // K splits
static constexpr int KCHUNK = VOCAB / KS;    // 256
static constexpr int NITER  = KCHUNK / 16;   // 16
static constexpr int NT     = 4;             // N tiles of 128 (pgemm grid = 500)

// k_front role boundaries (block index): convert then hist
static constexpr int FB_CONV = 8000;
static constexpr int FB_HIST = FB_CONV + 1024;

// k_mid role boundaries: pgemm then query gather (2 rows/block)
static constexpr int MB_GEMM   = NT * KS;            // 500
static constexpr int MB_GATHER = MB_GEMM + QN / 2;   // + 1024

// k_out tiling: 64q x 64c x 32d per block, 16 d-splits -> grid 512
static constexpr int DS  = 16;               // d splits (32 dims each)
static constexpr int QB  = QN / 64;          // 32 q blocks
static constexpr int TP2 = 36;               // padded tile row stride (floats)

// Scratch (__device__ globals; zero-initialized at module load).
// INVARIANT: g_W and g_cnt are ZERO at entry of every kernel_launch call —
// module-load zeros for call 1; k_reduce re-zeros W, k_out re-zeros cnt.
__device__ __align__(16) __half g_table_h[VOCAB * D]; // fp16 shadow (32.8 MB)
__device__ __align__(16) __half g_W[NC * VOCAB];      // class-token histogram (4.1 MB)
__device__ __align__(16) float g_pp[KS * NC * D];     // split-K partials (16.4 MB)
__device__ float g_proto[NC * D];   // normalized prototypes (after k_reduce)
__device__ float g_cnt[NC];         // per-class support-row counts
__device__ float g_qemb[QN * D];    // query embeddings (mean-pooled)
__device__ float g_q2[QN];          // ||q||^2

__device__ __forceinline__ unsigned smem_u32(const void* p) {
    unsigned a;
    asm("{ .reg .u64 t; cvta.to.shared.u64 t, %1; cvt.u32.u64 %0, t; }"
        : "=r"(a) : "l"(p));
    return a;
}

// ---------------------------------------------------------------- kernel 1
// Front end: [0,8000) table fp32 -> fp16 convert; [8000,9024) support hist.
__global__ __launch_bounds__(256) void k_front(
    const int*   __restrict__ s_toks,
    const int*   __restrict__ labels,
    const float* __restrict__ table)
{
    const int bid = blockIdx.x;
    const int tid = threadIdx.x;

    if (bid < FB_CONV) {
        const int i = bid * 256 + tid;               // 8-elem group id
        const float4* sp4 = (const float4*)table;
        float4 a = sp4[2 * i];
        float4 b = sp4[2 * i + 1];
        __half2 h0 = __floats2half2_rn(a.x, a.y);
        __half2 h1 = __floats2half2_rn(a.z, a.w);
        __half2 h2 = __floats2half2_rn(b.x, b.y);
        __half2 h3 = __floats2half2_rn(b.z, b.w);
        uint4 o;
        o.x = *(const unsigned*)&h0;
        o.y = *(const unsigned*)&h1;
        o.z = *(const unsigned*)&h2;
        o.w = *(const unsigned*)&h3;
        ((uint4*)g_table_h)[i] = o;
    } else {
        const int t   = (bid - FB_CONV) * 256 + tid; // < SN*TOK
        const int row = t >> 6;
        const int c   = labels[row];
        const int v   = s_toks[t];
        const int idx = c * VOCAB + v;
        __half2* p = (__half2*)(g_W + (idx & ~1));
        const __half2 one = (idx & 1)
            ? __halves2half2(__ushort_as_half(0), __float2half(1.0f))
            : __halves2half2(__float2half(1.0f), __ushort_as_half(0));
        atomicAdd(p, one);
        if ((t & 63) == 0) atomicAdd(&g_cnt[c], 1.0f);
    }
}

// ---------------------------------------------------------------- kernel 2
// Mid stage, role-split: [0,500) split-K tensor-core proto GEMM;
// [500,1524) query gather on the fp16 shadow (2 rows/block).
// Gather also initializes out[q][*] = -q2[q] (base for k_out's atomics).
__global__ __launch_bounds__(256) void k_mid(
    const int* __restrict__ q_toks, float* __restrict__ out)
{
    const int tid = threadIdx.x;

    if (blockIdx.x < MB_GEMM) {
        // ================= proto GEMM (proven R9-R14 core) =================
        __shared__ __half sA[64 * 24];
        __shared__ __half sB[16 * 136];

        const int bn = (blockIdx.x & (NT - 1)) * 128;
        const int kb = blockIdx.x / NT;
        const int k0 = kb * KCHUNK;
        const int warp = tid >> 5;
        const int lane = tid & 31;
        const int wr   = warp & 3;
        const int wn   = warp >> 2;
        const int g    = lane >> 2;
        const int tg   = lane & 3;

        const int arow  = (tid & 127) >> 1;
        const int acol8 = (tid & 1) * 8;
        const int brow  = tid >> 4;
        const int bcol8 = (tid & 15) * 8;

        const __half* aSrc = g_W + (size_t)arow * VOCAB + k0 + acol8;
        const __half* bSrc = g_table_h + (size_t)(k0 + brow) * D + bn + bcol8;

        const int am = lane >> 3, ar = lane & 7;
        const unsigned aAddr = smem_u32(sA + (wr * 16 + ar + 8 * (am & 1)) * 24
                                           + 8 * (am >> 1));
        const unsigned bAddr = smem_u32(sB + (lane & 15) * 136 + wn * 64);

        float acc[8][4];
        #pragma unroll
        for (int s = 0; s < 8; ++s)
            acc[s][0] = acc[s][1] = acc[s][2] = acc[s][3] = 0.0f;

        uint4 va = make_uint4(0, 0, 0, 0);
        if (tid < 128) va = *(const uint4*)(aSrc);
        uint4 vb = *(const uint4*)(bSrc);

        for (int it = 0; it < NITER; ++it) {
            __syncthreads();
            if (tid < 128) *(uint4*)(sA + arow * 24 + acol8) = va;
            *(uint4*)(sB + brow * 136 + bcol8) = vb;
            __syncthreads();

            const int kn = min((it + 1) * 16, KCHUNK - 16);
            if (tid < 128) va = *(const uint4*)(aSrc + kn);
            vb = *(const uint4*)(bSrc + (size_t)kn * D);

            unsigned a0, a1, a2, a3;
            asm volatile("ldmatrix.sync.aligned.m8n8.x4.shared.b16 {%0,%1,%2,%3}, [%4];"
                         : "=r"(a0), "=r"(a1), "=r"(a2), "=r"(a3) : "r"(aAddr));
            #pragma unroll
            for (int s = 0; s < 8; ++s) {
                unsigned b0, b1;
                asm volatile("ldmatrix.sync.aligned.m8n8.x2.trans.shared.b16 {%0,%1}, [%2];"
                             : "=r"(b0), "=r"(b1) : "r"(bAddr + s * 16));
                asm volatile(
                    "mma.sync.aligned.m16n8k16.row.col.f32.f16.f16.f32 "
                    "{%0,%1,%2,%3}, {%4,%5,%6,%7}, {%8,%9}, {%0,%1,%2,%3};"
                    : "+f"(acc[s][0]), "+f"(acc[s][1]), "+f"(acc[s][2]), "+f"(acc[s][3])
                    : "r"(a0), "r"(a1), "r"(a2), "r"(a3), "r"(b0), "r"(b1));
            }
        }

        float* base = g_pp + (size_t)kb * NC * D;
        #pragma unroll
        for (int s = 0; s < 8; ++s) {
            const int col = bn + wn * 64 + s * 8 + tg * 2;
            *(float2*)(base + (wr * 16 + g) * D + col)     =
                make_float2(acc[s][0], acc[s][1]);
            *(float2*)(base + (wr * 16 + g + 8) * D + col) =
                make_float2(acc[s][2], acc[s][3]);
        }
    } else {
        // ================= query gather on fp16 shadow =================
        const int bid = blockIdx.x - MB_GEMM;
        const int h   = tid >> 7;            // 0 or 1
        const int lt  = tid & 127;           // lane within half-block
        const int row = bid * 2 + h;

        __shared__ int sh_tok[2][TOK];
        __shared__ float sp[8];
        __shared__ float sq2[2];
        if (lt < TOK)
            sh_tok[h][lt] = q_toks[(size_t)row * TOK + lt];
        __syncthreads();

        float a0 = 0.f, a1 = 0.f, a2 = 0.f, a3 = 0.f;
        #pragma unroll 8
        for (int j = 0; j < TOK; ++j) {
            const uint2* r = (const uint2*)(g_table_h + (size_t)sh_tok[h][j] * D);
            uint2 v = r[lt];                           // 4 halves
            float2 f0 = __half22float2(*(const __half2*)&v.x);
            float2 f1 = __half22float2(*(const __half2*)&v.y);
            a0 += f0.x; a1 += f0.y; a2 += f1.x; a3 += f1.y;
        }
        const float s = 1.0f / (float)TOK;
        a0 *= s; a1 *= s; a2 *= s; a3 *= s;
        ((float4*)(g_qemb + (size_t)row * D))[lt] = make_float4(a0, a1, a2, a3);

        float qq = a0*a0 + a1*a1 + a2*a2 + a3*a3;
        #pragma unroll
        for (int o = 16; o > 0; o >>= 1)
            qq += __shfl_down_sync(0xFFFFFFFFu, qq, o);
        if ((tid & 31) == 0) sp[tid >> 5] = qq;
        __syncthreads();
        if (lt == 0) {
            const float v = sp[h * 4] + sp[h * 4 + 1] + sp[h * 4 + 2] + sp[h * 4 + 3];
            g_q2[row] = v;
            sq2[h] = v;
        }
        __syncthreads();
        // out init: out[row][c] = -q2[row] for all 64 classes (16 float4).
        const float nq2 = -sq2[h];
        if (lt < 16)
            ((float4*)(out + (size_t)row * NC))[lt] =
                make_float4(nq2, nq2, nq2, nq2);
    }
}

// ---------------------------------------------------------------- kernel 3
// Fold split-K partials + 1/(64*cnt) normalization into g_proto.
// Also re-zero g_W (not touched by this kernel) for the next call.
__global__ __launch_bounds__(256) void k_reduce()
{
    const int t = blockIdx.x * blockDim.x + threadIdx.x;   // < 32768 = NC*D
    float a = 0.0f;
    #pragma unroll 5
    for (int s = 0; s < KS; ++s) a += g_pp[(size_t)s * NC * D + t];
    const int c = t >> 9;                                  // t / D
    g_proto[t] = a / (64.0f * fmaxf(g_cnt[c], 1.0f));

    // W re-zero: g_W = NC*VOCAB/8 = 256000 uint4 (guarded)
    uint4* w4 = (uint4*)g_W;
    #pragma unroll
    for (int r = 0; r < 8; ++r) {
        const int idx = t + r * 32768;
        if (idx < NC * VOCAB / 8) w4[idx] = make_uint4(0, 0, 0, 0);
    }
}

// ---------------------------------------------------------------- kernel 4
// Distance GEMM: block = 64q x 64c x 32d; grid = 32 q-blocks x 16 d-splits
// = 512 (~3.5 blocks/SM). 4q x 4c register tile (the proven 2.0 FMA/LDS
// ratio). Adds 2*dot_s - p2_s atomically onto the -q2 base.
// Trailing duty: zero g_cnt for the next call.
__global__ __launch_bounds__(256) void k_out(float* __restrict__ out)
{
    __shared__ __align__(16) float q_s[64 * TP2];  // 64 x 32, stride 36
    __shared__ __align__(16) float p_s[64 * TP2];
    __shared__ float s_pp[NC];

    const int tid = threadIdx.x;
    const int q0  = (blockIdx.x >> 4) * 64;       // q block
    const int d0  = (blockIdx.x & 15) * 32;       // d split

    // Stage tiles: 64 rows x 8 float4 each; 2 float4 per thread per array.
    #pragma unroll
    for (int r = 0; r < 2; ++r) {
        const int idx  = tid + r * 256;           // < 512
        const int row  = idx >> 3;
        const int col4 = idx & 7;
        ((float4*)(q_s + row * TP2))[col4] =
            ((const float4*)(g_qemb + (size_t)(q0 + row) * D + d0))[col4];
        ((float4*)(p_s + row * TP2))[col4] =
            ((const float4*)(g_proto + (size_t)row * D + d0))[col4];
    }
    __syncthreads();

    const int tq = tid >> 4;       // 0..15 -> q rows [4tq, 4tq+4)
    const int tc = tid & 15;       // c rows tc, tc+16, tc+32, tc+48

    float acc[4][4];
    #pragma unroll
    for (int i = 0; i < 4; ++i)
        acc[i][0] = acc[i][1] = acc[i][2] = acc[i][3] = 0.0f;
    float pa0 = 0.f, pa1 = 0.f, pa2 = 0.f, pa3 = 0.f;

    #pragma unroll
    for (int d4 = 0; d4 < 8; ++d4) {
        float4 pv[4];
        #pragma unroll
        for (int j = 0; j < 4; ++j)
            pv[j] = ((const float4*)(p_s + (tc + 16 * j) * TP2))[d4];
        if (tq == 0) {   // p2 partials (one owner per class)
            pa0 += pv[0].x*pv[0].x + pv[0].y*pv[0].y + pv[0].z*pv[0].z + pv[0].w*pv[0].w;
            pa1 += pv[1].x*pv[1].x + pv[1].y*pv[1].y + pv[1].z*pv[1].z + pv[1].w*pv[1].w;
            pa2 += pv[2].x*pv[2].x + pv[2].y*pv[2].y + pv[2].z*pv[2].z + pv[2].w*pv[2].w;
            pa3 += pv[3].x*pv[3].x + pv[3].y*pv[3].y + pv[3].z*pv[3].z + pv[3].w*pv[3].w;
        }
        #pragma unroll
        for (int i = 0; i < 4; ++i) {
            const float4 qv = ((const float4*)(q_s + (4 * tq + i) * TP2))[d4];
            #pragma unroll
            for (int j = 0; j < 4; ++j)
                acc[i][j] += qv.x*pv[j].x + qv.y*pv[j].y
                           + qv.z*pv[j].z + qv.w*pv[j].w;
        }
    }

    if (tq == 0) {
        s_pp[tc]      = pa0;
        s_pp[tc + 16] = pa1;
        s_pp[tc + 32] = pa2;
        s_pp[tc + 48] = pa3;
    }
    __syncthreads();

    #pragma unroll
    for (int i = 0; i < 4; ++i) {
        const int q = q0 + 4 * tq + i;
        #pragma unroll
        for (int j = 0; j < 4; ++j) {
            const int c = tc + 16 * j;
            atomicAdd(out + (size_t)q * NC + c, 2.0f * acc[i][j] - s_pp[c]);
        }
    }

    // cnt re-zero for next call (cnt is not read by this kernel).
    const int t = blockIdx.x * 256 + tid;
    if (t < NC) g_cnt[t] = 0.0f;
}

// ----------------------------------------------------------------
extern "C" void kernel_launch(void* const* d_in, const int* in_sizes, int n_in,
                              void* d_out, int out_size)
{
    // JAX x64 disabled -> "int64" tensors are int32 on the wire.
    const int*   query   = (const int*)d_in[0];
    const int*   support = (const int*)d_in[1];
    const int*   labels  = (const int*)d_in[2];
    const float* table   = (const float*)d_in[3];
    float* out = (float*)d_out;

    k_front<<<FB_HIST, 256>>>(support, labels, table);  // convert + hist
    k_mid<<<MB_GATHER, 256>>>(query, out);              // GEMM ∥ gather (+init)
    k_reduce<<<NC * D / 256, 256>>>();                  // fold splits + W zero
    k_out<<<QB * DS, 256>>>(out);                       // distances
}